// round 16
// baseline (speedup 1.0000x reference)
#include <cuda_runtime.h>

#define HW_    262144          // 512*512 floats per channel
#define C_     9
#define N_     16
#define NCH_   144             // N_*C_
#define NT_    1024            // threads per CTA
#define SLOTS_ 256             // per-thread candidate slots (exact: HW_/NT_, retry-safe)
#define PSW_   911             // phase-2 words per CTA (911*9 = 8199 >= 8192)

// Scratch (device globals — no allocation allowed)
__device__ unsigned long long g_cand[(size_t)NCH_ * HW_];  // per-thread regions
// Bitmap (per channel, 8192 words): word[ob*1024 + t], bit j*4+e
//   <-> element ((ob*8192 + j*1024 + t)*4 + e),  ob:0..7, j:0..7, t:0..1023
__device__ unsigned g_bitmap[NCH_ * (HW_ / 32)];
__device__ unsigned g_scnt[N_];                            // per-sample arrival counts
__device__ unsigned g_sgen[N_];                            // per-sample generations

// Order-preserving float->uint key (ascending key == ascending float)
static __device__ __forceinline__ unsigned f2key(float f) {
    unsigned u = __float_as_uint(f);
    return (u & 0x80000000u) ? ~u : (u | 0x80000000u);
}

// Packed f32x2 fma: returns fma(a2, b2, c2) per 32-bit lane (one FFMA2)
static __device__ __forceinline__ unsigned long long fma2(
    unsigned long long a, unsigned long long b, unsigned long long c) {
    unsigned long long d;
    asm("fma.rn.f32x2 %0, %1, %2, %3;" : "=l"(d) : "l"(a), "l"(b), "l"(c));
    return d;
}

// Sign-bit movemask of 4 packed f32 (d01 = lanes x,y; d23 = lanes z,w) -> nibble
static __device__ __forceinline__ unsigned mm4(unsigned long long d01,
                                               unsigned long long d23) {
    unsigned a = __byte_perm((unsigned)d01, (unsigned)(d01 >> 32), 0x0073);
    unsigned b = __byte_perm((unsigned)d23, (unsigned)(d23 >> 32), 0x0073);
    unsigned w = __byte_perm(a, b, 0x5410);   // sign bytes of x,y,z,w
    return ((w & 0x80808080u) * 0x00204081u) >> 28;
}

// 32-byte L2 load with evict_last priority: pins the line in L2 so the
// streaming (evict-normal) inp traffic cannot victimize it. Legal forms on
// sm_103a are .v8.b32 / .v4.b64 — use v4.b64.
static __device__ __forceinline__ void l2_pin_32B(const void* p) {
    unsigned long long a, b, c, d;
    asm volatile("ld.global.nc.L2::evict_last.v4.b64 {%0,%1,%2,%3}, [%4];"
                 : "=l"(a), "=l"(b), "=l"(c), "=l"(d) : "l"(p));
}

// Block-wide "find bin containing rank-from-top" over hist[0..nb), nb in {2048,1024}.
// Result: aux[0]=bin, aux[1]=remaining rank (1-indexed in bin). All NT_ threads call.
static __device__ __forceinline__ void block_find_bin(
    unsigned* hist, int nb, unsigned rank,
    unsigned* sgrp, unsigned* aux, int tid, int lane, int w)
{
    unsigned s = (nb == 2048) ? (hist[tid * 2] + hist[tid * 2 + 1]) : hist[tid];
    sgrp[tid] = s;
    __syncthreads();
    if (w == 0) {
        unsigned sup = 0;
        #pragma unroll 4
        for (int j = 0; j < 32; j++) sup += sgrp[lane * 32 + j];
        unsigned v = sup;                    // inclusive suffix scan (lane31 = top bins)
        #pragma unroll
        for (int off = 1; off < 32; off <<= 1) {
            unsigned t = __shfl_down_sync(0xffffffffu, v, off);
            if (lane + off < 32) v += t;
        }
        unsigned cumAbove = v - sup;
        bool hit = (cumAbove < rank) && (cumAbove + sup >= rank);
        unsigned bal = __ballot_sync(0xffffffffu, hit);
        int Ls = __ffs(bal) - 1;
        if (lane == Ls) {
            unsigned cum = cumAbove;
            for (int g = Ls * 32 + 31; ; g--) {
                unsigned sg = sgrp[g];
                if (cum + sg >= rank) {
                    int B = (nb == 2048) ? 2 : 1;
                    for (int b = g * B + B - 1; ; b--) {
                        unsigned h = hist[b];
                        if (cum + h >= rank) { aux[0] = (unsigned)b; aux[1] = rank - cum; break; }
                        cum += h;
                    }
                    break;
                }
                cum += sg;
            }
        }
    }
    __syncthreads();
}

__global__ void __launch_bounds__(NT_) k_fused(const float* __restrict__ inp,
                                               const float* __restrict__ ratio,
                                               const float* __restrict__ x,
                                               float* __restrict__ out)
{
    __shared__ unsigned hist[2048];
    __shared__ unsigned sgrp[NT_];
    __shared__ unsigned aux[4];        // [0]=cnt_hi / bin, [1]=m / rank

    int ch = blockIdx.x, n = ch / C_;
    int tid = threadIdx.x, w = tid >> 5, lane = tid & 31;

    // k: replicate reference f32 arithmetic exactly
    float f_p = floorf(ratio[n] * 262144.0f);
    int k = (int)floorf(f_p * 0.15f);
    bool k0 = (k <= 0);

    const ulonglong2* p = (const ulonglong2*)(inp + (size_t)ch * HW_);
    const float INF = __int_as_float(0x7F800000);

    // Analytic bracket around the k-th largest for N(0,1)-like data. Correctness
    // is guaranteed by the count-check + full-range retry, not by normality.
    float lo_f, hi_f;
    if (k0) {
        lo_f = hi_f = 1.0f;            // reference: thr = 1.0 when k == 0 (strict >, exact)
    } else {
        float q = (float)k * (1.0f / 262144.0f);
        float t = sqrtf(-2.0f * logf(q));               // A&S 26.2.23
        float z = t - (2.515517f + 0.802853f * t + 0.010328f * t * t)
                    / (1.0f + 1.432788f * t + 0.189269f * t * t + 0.001308f * t * t * t);
        float phi = 0.3989423f * expf(-0.5f * z * z);
        float delta = 0.008f + 10.0f * sqrtf((float)k) / (262144.0f * phi);
        lo_f = z - delta; hi_f = z + delta;
    }

    const unsigned long long NEG1 = 0xBF800000BF800000ull;   // (-1.0f, -1.0f)
    unsigned long long HI2, LO2;
    {
        unsigned hu = __float_as_uint(hi_f), lu = __float_as_uint(lo_f);
        HI2 = ((unsigned long long)hu << 32) | hu;
        LO2 = ((unsigned long long)lu << 32) | lu;
    }

    // ---- pin all of x (16 MB) into L2 with evict_last during the stream ----
    // 524288 chunks of 32B over 147456 threads (~3.6/thread). The evict-normal
    // inp stream recycles its own lines; x stays resident for phase 2.
    {
        const char* xb = (const char*)x;
        for (int i = blockIdx.x * NT_ + tid; i < 524288; i += NCH_ * NT_)
            l2_pin_32B(xb + (size_t)i * 32);
    }

    unsigned long long* myc = g_cand + (size_t)ch * HW_ + (size_t)tid * SLOTS_;
    unsigned* gbch = g_bitmap + (size_t)ch * 8192;
    unsigned cnt_hi, m;
    int mycap;
    for (int attempt = 0; ; attempt++) {
        if (tid == 0) { aux[0] = 0; aux[1] = 0; }
        __syncthreads();
        unsigned mycnt = 0;
        mycap = 0;
        #pragma unroll 1
        for (int ob = 0; ob < 8; ob++) {           // 8 outer blocks of 8*NT_ float4s
            int base = ob * 8 * NT_;
            ulonglong2 v0 = p[base + tid];
            ulonglong2 v1 = p[base + NT_ + tid];
            ulonglong2 v2 = p[base + 2 * NT_ + tid];
            ulonglong2 v3 = p[base + 3 * NT_ + tid];
            ulonglong2 v4 = p[base + 4 * NT_ + tid];
            ulonglong2 v5 = p[base + 5 * NT_ + tid];
            ulonglong2 v6 = p[base + 6 * NT_ + tid];
            ulonglong2 v7 = p[base + 7 * NT_ + tid];
            unsigned word = 0;
            #pragma unroll
            for (int j = 0; j < 8; j++) {
                ulonglong2 v = (j == 0) ? v0 : (j == 1) ? v1 : (j == 2) ? v2 : (j == 3) ? v3
                             : (j == 4) ? v4 : (j == 5) ? v5 : (j == 6) ? v6 : v7;
                unsigned hi4 = mm4(fma2(v.x, NEG1, HI2), fma2(v.y, NEG1, HI2));
                unsigned lo4 = mm4(fma2(v.x, NEG1, LO2), fma2(v.y, NEG1, LO2));
                word |= hi4 << (j * 4);
                unsigned cn = lo4 & ~hi4;
                if (cn) {                           // rare (~0.2-2%)
                    int idx4 = base + j * NT_ + tid;
                    float fx = __uint_as_float((unsigned)v.x);
                    float fy = __uint_as_float((unsigned)(v.x >> 32));
                    float fz = __uint_as_float((unsigned)v.y);
                    float fw = __uint_as_float((unsigned)(v.y >> 32));
                    if (cn & 1u) myc[mycap++] = ((unsigned long long)f2key(fx) << 32) | (unsigned)(idx4 * 4 + 0);
                    if (cn & 2u) myc[mycap++] = ((unsigned long long)f2key(fy) << 32) | (unsigned)(idx4 * 4 + 1);
                    if (cn & 4u) myc[mycap++] = ((unsigned long long)f2key(fz) << 32) | (unsigned)(idx4 * 4 + 2);
                    if (cn & 8u) myc[mycap++] = ((unsigned long long)f2key(fw) << 32) | (unsigned)(idx4 * 4 + 3);
                }
            }
            mycnt += __popc(word);
            gbch[ob * NT_ + tid] = word;            // coalesced, no cross-lane ops
        }
        // Block totals
        unsigned mc = (unsigned)mycap;
        #pragma unroll
        for (int off = 16; off; off >>= 1) {
            mycnt += __shfl_down_sync(0xffffffffu, mycnt, off);
            mc    += __shfl_down_sync(0xffffffffu, mc, off);
        }
        if (lane == 0) { atomicAdd(&aux[0], mycnt); atomicAdd(&aux[1], mc); }
        __syncthreads();
        cnt_hi = aux[0]; m = aux[1];
        if (k0) break;
        if ((cnt_hi < (unsigned)k && cnt_hi + m >= (unsigned)k) || attempt >= 1) break;
        lo_f = -INF; hi_f = INF;       // deterministic widen (count-check guarantee)
        {
            unsigned hu = __float_as_uint(hi_f), lu = __float_as_uint(lo_f);
            HI2 = ((unsigned long long)hu << 32) | hu;
            LO2 = ((unsigned long long)lu << 32) | lu;
        }
        __syncthreads();
    }

    // ---- exact threshold among candidates (11+11+10-bit radix), then fixups ----
    if (!k0) {
        unsigned r = (unsigned)k - cnt_hi;
        for (int i = tid; i < 2048; i += NT_) hist[i] = 0;
        __syncthreads();
        for (int i = 0; i < mycap; i++)
            atomicAdd(&hist[(unsigned)(myc[i] >> 32) >> 21], 1u);
        __syncthreads();
        block_find_bin(hist, 2048, r, sgrp, aux, tid, lane, w);
        unsigned bA = aux[0], rA = aux[1];
        __syncthreads();

        for (int i = tid; i < 2048; i += NT_) hist[i] = 0;
        __syncthreads();
        for (int i = 0; i < mycap; i++) {
            unsigned key = (unsigned)(myc[i] >> 32);
            if ((key >> 21) == bA) atomicAdd(&hist[(key >> 10) & 0x7FFu], 1u);
        }
        __syncthreads();
        block_find_bin(hist, 2048, rA, sgrp, aux, tid, lane, w);
        unsigned bB = aux[0], rB = aux[1];
        __syncthreads();

        for (int i = tid; i < 1024; i += NT_) hist[i] = 0;
        __syncthreads();
        for (int i = 0; i < mycap; i++) {
            unsigned key = (unsigned)(myc[i] >> 32);
            if ((key >> 21) == bA && ((key >> 10) & 0x7FFu) == bB)
                atomicAdd(&hist[key & 0x3FFu], 1u);
        }
        __syncthreads();
        block_find_bin(hist, 1024, rB, sgrp, aux, tid, lane, w);
        unsigned thrkey = (bA << 21) | (bB << 10) | aux[0];    // exact k-th largest
        __syncthreads();

        // Fixups: candidates above exact threshold -> set bit in bitmap
        for (int i = 0; i < mycap; i++) {
            unsigned long long cc = myc[i];
            if ((unsigned)(cc >> 32) > thrkey) {
                unsigned pos = (unsigned)cc & 0x3FFFFu;
                unsigned f4 = pos >> 2, e = pos & 3u;
                unsigned t  = f4 & 1023u, j = (f4 >> 10) & 7u, ob = f4 >> 13;
                atomicOr(&gbch[ob * NT_ + t], 1u << (j * 4 + e));
            }
        }
    }

    // ---- per-sample barrier: sync only with the 8 sibling CTAs of sample n ----
    __threadfence();
    __syncthreads();
    if (tid == 0) {
        unsigned gen = *(volatile unsigned*)&g_sgen[n];
        unsigned t = atomicAdd(&g_scnt[n], 1u);
        if (t == C_ - 1) {                       // 9th arrival for this sample
            atomicExch(&g_scnt[n], 0u);          // reset for next graph replay
            __threadfence();
            atomicAdd(&g_sgen[n], 1u);
        } else {
            while (*(volatile unsigned*)&g_sgen[n] == gen) __nanosleep(32);
        }
        __threadfence();
    }
    __syncthreads();

    // ---- phase 2: 9 sibling CTAs split sample n's mask work (<=1 item/thread) ----
    {
        int c9 = ch - n * C_;                    // 0..8
        int wp = c9 * PSW_ + tid;
        if (wp < (c9 + 1) * PSW_ && wp < 8192) {
            int ob = wp >> 10, t = wp & 1023;
            const unsigned* bm = g_bitmap + (size_t)n * C_ * 8192 + wp;
            unsigned wrd = 0;
            #pragma unroll
            for (int c = 0; c < C_; c++) wrd |= __ldg(bm + (size_t)c * 8192);
            const float4* xp = (const float4*)x + ((size_t)n << 16) + ob * 8192 + t;
            float4*       op = (float4*)out     + ((size_t)n << 16) + ob * 8192 + t;
            #pragma unroll
            for (int j = 0; j < 8; j++) {
                float4 xv = xp[j * 1024];
                unsigned nib = (wrd >> (j * 4)) & 0xFu;
                float4 o;
                o.x = (nib & 1u) ? 0.0f : xv.x;
                o.y = (nib & 2u) ? 0.0f : xv.y;
                o.z = (nib & 4u) ? 0.0f : xv.z;
                o.w = (nib & 8u) ? 0.0f : xv.w;
                op[j * 1024] = o;
            }
        }
    }
}

extern "C" void kernel_launch(void* const* d_in, const int* in_sizes, int n_in,
                              void* d_out, int out_size) {
    const float* inp   = (const float*)d_in[0];   // [16,9,512,512]
    const float* x     = (const float*)d_in[1];   // [16,1,512,512]
    const float* ratio = (const float*)d_in[2];   // [16]
    float* out = (float*)d_out;

    k_fused<<<NCH_, NT_>>>(inp, ratio, x, out);
}

// round 17
// speedup vs baseline: 1.1640x; 1.1640x over previous
#include <cuda_runtime.h>

#define HW_    262144          // 512*512 floats per channel
#define C_     9
#define N_     16
#define NCH_   144             // N_*C_
#define NT_    1024            // threads per CTA
#define SLOTS_ 256             // per-thread candidate slots (exact: HW_/NT_, retry-safe)
#define PSW_   911             // phase-2 words per CTA (911*9 = 8199 >= 8192)

// Scratch (device globals — no allocation allowed)
// Candidates, lane-interleaved: slot i of lane l, warp w of channel ch lives at
//   g_cand[ch*HW_ + w*32*SLOTS_ + i*32 + l]   -> warp-coalesced writes & reads
__device__ unsigned long long g_cand[(size_t)NCH_ * HW_];
// Bitmap (per channel, 8192 words): word[ob*1024 + t], bit j*4+e
//   <-> element ((ob*8192 + j*1024 + t)*4 + e),  ob:0..7, j:0..7, t:0..1023
__device__ unsigned g_bitmap[NCH_ * (HW_ / 32)];
__device__ unsigned g_scnt[N_];                            // per-sample arrival counts
__device__ unsigned g_sgen[N_];                            // per-sample generations

// Order-preserving float->uint key (ascending key == ascending float)
static __device__ __forceinline__ unsigned f2key(float f) {
    unsigned u = __float_as_uint(f);
    return (u & 0x80000000u) ? ~u : (u | 0x80000000u);
}

// Packed f32x2 fma: returns fma(a2, b2, c2) per 32-bit lane (one FFMA2)
static __device__ __forceinline__ unsigned long long fma2(
    unsigned long long a, unsigned long long b, unsigned long long c) {
    unsigned long long d;
    asm("fma.rn.f32x2 %0, %1, %2, %3;" : "=l"(d) : "l"(a), "l"(b), "l"(c));
    return d;
}

// Sign-bit movemask of 4 packed f32 (d01 = lanes x,y; d23 = lanes z,w) -> nibble
static __device__ __forceinline__ unsigned mm4(unsigned long long d01,
                                               unsigned long long d23) {
    unsigned a = __byte_perm((unsigned)d01, (unsigned)(d01 >> 32), 0x0073);
    unsigned b = __byte_perm((unsigned)d23, (unsigned)(d23 >> 32), 0x0073);
    unsigned w = __byte_perm(a, b, 0x5410);   // sign bytes of x,y,z,w
    return ((w & 0x80808080u) * 0x00204081u) >> 28;
}

// Block-wide "find bin containing rank-from-top" over hist[0..nb), nb in {2048,1024}.
// Result: aux[0]=bin, aux[1]=remaining rank (1-indexed in bin). All NT_ threads call.
static __device__ __forceinline__ void block_find_bin(
    unsigned* hist, int nb, unsigned rank,
    unsigned* sgrp, unsigned* aux, int tid, int lane, int w)
{
    unsigned s = (nb == 2048) ? (hist[tid * 2] + hist[tid * 2 + 1]) : hist[tid];
    sgrp[tid] = s;
    __syncthreads();
    if (w == 0) {
        unsigned sup = 0;
        #pragma unroll 4
        for (int j = 0; j < 32; j++) sup += sgrp[lane * 32 + j];
        unsigned v = sup;                    // inclusive suffix scan (lane31 = top bins)
        #pragma unroll
        for (int off = 1; off < 32; off <<= 1) {
            unsigned t = __shfl_down_sync(0xffffffffu, v, off);
            if (lane + off < 32) v += t;
        }
        unsigned cumAbove = v - sup;
        bool hit = (cumAbove < rank) && (cumAbove + sup >= rank);
        unsigned bal = __ballot_sync(0xffffffffu, hit);
        int Ls = __ffs(bal) - 1;
        if (lane == Ls) {
            unsigned cum = cumAbove;
            for (int g = Ls * 32 + 31; ; g--) {
                unsigned sg = sgrp[g];
                if (cum + sg >= rank) {
                    int B = (nb == 2048) ? 2 : 1;
                    for (int b = g * B + B - 1; ; b--) {
                        unsigned h = hist[b];
                        if (cum + h >= rank) { aux[0] = (unsigned)b; aux[1] = rank - cum; break; }
                        cum += h;
                    }
                    break;
                }
                cum += sg;
            }
        }
    }
    __syncthreads();
}

__global__ void __launch_bounds__(NT_) k_fused(const float* __restrict__ inp,
                                               const float* __restrict__ ratio,
                                               const float* __restrict__ x,
                                               float* __restrict__ out)
{
    __shared__ unsigned hist[2048];
    __shared__ unsigned sgrp[NT_];
    __shared__ unsigned aux[4];        // [0]=cnt_hi / bin, [1]=m / rank

    int ch = blockIdx.x, n = ch / C_;
    int tid = threadIdx.x, w = tid >> 5, lane = tid & 31;

    // k: replicate reference f32 arithmetic exactly
    float f_p = floorf(ratio[n] * 262144.0f);
    int k = (int)floorf(f_p * 0.15f);
    bool k0 = (k <= 0);

    const ulonglong2* p = (const ulonglong2*)(inp + (size_t)ch * HW_);
    const float INF = __int_as_float(0x7F800000);

    // Analytic bracket around the k-th largest for N(0,1)-like data (5-sigma
    // empirical-quantile margin + quantile-approx slack). Correctness is
    // guaranteed by the count-check + full-range retry, not by normality.
    float lo_f, hi_f;
    if (k0) {
        lo_f = hi_f = 1.0f;            // reference: thr = 1.0 when k == 0 (strict >, exact)
    } else {
        float q = (float)k * (1.0f / 262144.0f);
        float t = sqrtf(-2.0f * logf(q));               // A&S 26.2.23
        float z = t - (2.515517f + 0.802853f * t + 0.010328f * t * t)
                    / (1.0f + 1.432788f * t + 0.189269f * t * t + 0.001308f * t * t * t);
        float phi = 0.3989423f * expf(-0.5f * z * z);
        float delta = 0.004f + 5.0f * sqrtf((float)k) / (262144.0f * phi);
        lo_f = z - delta; hi_f = z + delta;
    }

    const unsigned long long NEG1 = 0xBF800000BF800000ull;   // (-1.0f, -1.0f)
    unsigned long long HI2, LO2;
    {
        unsigned hu = __float_as_uint(hi_f), lu = __float_as_uint(lo_f);
        HI2 = ((unsigned long long)hu << 32) | hu;
        LO2 = ((unsigned long long)lu << 32) | lu;
    }

    // Lane-interleaved candidate region for this warp
    unsigned long long* wcd = g_cand + (size_t)ch * HW_ + (size_t)w * 32 * SLOTS_ + lane;
    unsigned* gbch = g_bitmap + (size_t)ch * 8192;
    unsigned cnt_hi, m;
    int mycap;
    for (int attempt = 0; ; attempt++) {
        if (tid == 0) { aux[0] = 0; aux[1] = 0; }
        __syncthreads();
        unsigned mycnt = 0;
        mycap = 0;
        #pragma unroll 1
        for (int ob = 0; ob < 8; ob++) {           // 8 outer blocks of 8*NT_ float4s
            int base = ob * 8 * NT_;
            ulonglong2 v0 = p[base + tid];
            ulonglong2 v1 = p[base + NT_ + tid];
            ulonglong2 v2 = p[base + 2 * NT_ + tid];
            ulonglong2 v3 = p[base + 3 * NT_ + tid];
            ulonglong2 v4 = p[base + 4 * NT_ + tid];
            ulonglong2 v5 = p[base + 5 * NT_ + tid];
            ulonglong2 v6 = p[base + 6 * NT_ + tid];
            ulonglong2 v7 = p[base + 7 * NT_ + tid];
            unsigned word = 0;
            #pragma unroll
            for (int j = 0; j < 8; j++) {
                ulonglong2 v = (j == 0) ? v0 : (j == 1) ? v1 : (j == 2) ? v2 : (j == 3) ? v3
                             : (j == 4) ? v4 : (j == 5) ? v5 : (j == 6) ? v6 : v7;
                unsigned hi4 = mm4(fma2(v.x, NEG1, HI2), fma2(v.y, NEG1, HI2));
                unsigned lo4 = mm4(fma2(v.x, NEG1, LO2), fma2(v.y, NEG1, LO2));
                word |= hi4 << (j * 4);
                unsigned cn = lo4 & ~hi4;
                if (cn) {                           // rare (~0.1-1%)
                    int idx4 = base + j * NT_ + tid;
                    float fx = __uint_as_float((unsigned)v.x);
                    float fy = __uint_as_float((unsigned)(v.x >> 32));
                    float fz = __uint_as_float((unsigned)v.y);
                    float fw = __uint_as_float((unsigned)(v.y >> 32));
                    if (cn & 1u) { wcd[(size_t)mycap * 32] = ((unsigned long long)f2key(fx) << 32) | (unsigned)(idx4 * 4 + 0); mycap++; }
                    if (cn & 2u) { wcd[(size_t)mycap * 32] = ((unsigned long long)f2key(fy) << 32) | (unsigned)(idx4 * 4 + 1); mycap++; }
                    if (cn & 4u) { wcd[(size_t)mycap * 32] = ((unsigned long long)f2key(fz) << 32) | (unsigned)(idx4 * 4 + 2); mycap++; }
                    if (cn & 8u) { wcd[(size_t)mycap * 32] = ((unsigned long long)f2key(fw) << 32) | (unsigned)(idx4 * 4 + 3); mycap++; }
                }
            }
            mycnt += __popc(word);
            gbch[ob * NT_ + tid] = word;            // coalesced, no cross-lane ops
        }
        // Block totals
        unsigned mc = (unsigned)mycap;
        #pragma unroll
        for (int off = 16; off; off >>= 1) {
            mycnt += __shfl_down_sync(0xffffffffu, mycnt, off);
            mc    += __shfl_down_sync(0xffffffffu, mc, off);
        }
        if (lane == 0) { atomicAdd(&aux[0], mycnt); atomicAdd(&aux[1], mc); }
        __syncthreads();
        cnt_hi = aux[0]; m = aux[1];
        if (k0) break;
        if ((cnt_hi < (unsigned)k && cnt_hi + m >= (unsigned)k) || attempt >= 1) break;
        lo_f = -INF; hi_f = INF;       // deterministic widen (count-check guarantee)
        {
            unsigned hu = __float_as_uint(hi_f), lu = __float_as_uint(lo_f);
            HI2 = ((unsigned long long)hu << 32) | hu;
            LO2 = ((unsigned long long)lu << 32) | lu;
        }
        __syncthreads();
    }

    // ---- exact threshold among candidates (11+11+10-bit radix), then fixups ----
    // All candidate loops are warp-coalesced: lanes read slot i simultaneously.
    if (!k0) {
        unsigned r = (unsigned)k - cnt_hi;
        for (int i = tid; i < 2048; i += NT_) hist[i] = 0;
        __syncthreads();
        for (int i = 0; i < mycap; i++)
            atomicAdd(&hist[(unsigned)(wcd[(size_t)i * 32] >> 32) >> 21], 1u);
        __syncthreads();
        block_find_bin(hist, 2048, r, sgrp, aux, tid, lane, w);
        unsigned bA = aux[0], rA = aux[1];
        __syncthreads();

        for (int i = tid; i < 2048; i += NT_) hist[i] = 0;
        __syncthreads();
        for (int i = 0; i < mycap; i++) {
            unsigned key = (unsigned)(wcd[(size_t)i * 32] >> 32);
            if ((key >> 21) == bA) atomicAdd(&hist[(key >> 10) & 0x7FFu], 1u);
        }
        __syncthreads();
        block_find_bin(hist, 2048, rA, sgrp, aux, tid, lane, w);
        unsigned bB = aux[0], rB = aux[1];
        __syncthreads();

        for (int i = tid; i < 1024; i += NT_) hist[i] = 0;
        __syncthreads();
        for (int i = 0; i < mycap; i++) {
            unsigned key = (unsigned)(wcd[(size_t)i * 32] >> 32);
            if ((key >> 21) == bA && ((key >> 10) & 0x7FFu) == bB)
                atomicAdd(&hist[key & 0x3FFu], 1u);
        }
        __syncthreads();
        block_find_bin(hist, 1024, rB, sgrp, aux, tid, lane, w);
        unsigned thrkey = (bA << 21) | (bB << 10) | aux[0];    // exact k-th largest
        __syncthreads();

        // Fixups: candidates above exact threshold -> set bit in bitmap
        for (int i = 0; i < mycap; i++) {
            unsigned long long cc = wcd[(size_t)i * 32];
            if ((unsigned)(cc >> 32) > thrkey) {
                unsigned pos = (unsigned)cc & 0x3FFFFu;
                unsigned f4 = pos >> 2, e = pos & 3u;
                unsigned t  = f4 & 1023u, j = (f4 >> 10) & 7u, ob = f4 >> 13;
                atomicOr(&gbch[ob * NT_ + t], 1u << (j * 4 + e));
            }
        }
    }

    // ---- per-sample barrier: sync only with the 8 sibling CTAs of sample n ----
    __threadfence();
    __syncthreads();
    if (tid == 0) {
        unsigned gen = *(volatile unsigned*)&g_sgen[n];
        unsigned t = atomicAdd(&g_scnt[n], 1u);
        if (t == C_ - 1) {                       // 9th arrival for this sample
            atomicExch(&g_scnt[n], 0u);          // reset for next graph replay
            __threadfence();
            atomicAdd(&g_sgen[n], 1u);
        } else {
            while (*(volatile unsigned*)&g_sgen[n] == gen) __nanosleep(32);
        }
        __threadfence();
    }
    __syncthreads();

    // ---- phase 2: 9 sibling CTAs split sample n's mask work (<=1 item/thread) ----
    {
        int c9 = ch - n * C_;                    // 0..8
        int wp = c9 * PSW_ + tid;
        if (wp < (c9 + 1) * PSW_ && wp < 8192) {
            int ob = wp >> 10, t = wp & 1023;
            const unsigned* bm = g_bitmap + (size_t)n * C_ * 8192 + wp;
            unsigned wrd = 0;
            #pragma unroll
            for (int c = 0; c < C_; c++) wrd |= __ldg(bm + (size_t)c * 8192);
            const float4* xp = (const float4*)x + ((size_t)n << 16) + ob * 8192 + t;
            float4*       op = (float4*)out     + ((size_t)n << 16) + ob * 8192 + t;
            #pragma unroll
            for (int j = 0; j < 8; j++) {
                float4 xv = xp[j * 1024];
                unsigned nib = (wrd >> (j * 4)) & 0xFu;
                float4 o;
                o.x = (nib & 1u) ? 0.0f : xv.x;
                o.y = (nib & 2u) ? 0.0f : xv.y;
                o.z = (nib & 4u) ? 0.0f : xv.z;
                o.w = (nib & 8u) ? 0.0f : xv.w;
                op[j * 1024] = o;
            }
        }
    }
}

extern "C" void kernel_launch(void* const* d_in, const int* in_sizes, int n_in,
                              void* d_out, int out_size) {
    const float* inp   = (const float*)d_in[0];   // [16,9,512,512]
    const float* x     = (const float*)d_in[1];   // [16,1,512,512]
    const float* ratio = (const float*)d_in[2];   // [16]
    float* out = (float*)d_out;

    k_fused<<<NCH_, NT_>>>(inp, ratio, x, out);
}